// round 9
// baseline (speedup 1.0000x reference)
#include <cuda_runtime.h>
#include <cuda_bf16.h>
#include <cstdint>

// Shapes fixed by dataset: L_F=32, HOP=16, DELTA=3, L_S=96, COND=32, GH=64, B=128, T=48000
// Nf = 2999, Ns = 999
#define BSZ    128
#define NS_MAX 999
#define NF_MAX 2999

typedef unsigned long long u64t;

// ---------------- packed f32x2 helpers (sm_103a FFMA2 path) ----------------
__device__ __forceinline__ u64t ffma2(u64t a, u64t b, u64t c) {
    u64t d; asm("fma.rn.f32x2 %0, %1, %2, %3;" : "=l"(d) : "l"(a), "l"(b), "l"(c)); return d;
}
__device__ __forceinline__ u64t fadd2(u64t a, u64t b) {
    u64t d; asm("add.rn.f32x2 %0, %1, %2;" : "=l"(d) : "l"(a), "l"(b)); return d;
}
__device__ __forceinline__ u64t fpack2(float lo, float hi) {
    u64t d; asm("mov.b64 %0, {%1, %2};" : "=l"(d) : "f"(lo), "f"(hi)); return d;
}
__device__ __forceinline__ float2 funpack2(u64t v) {
    float2 f; asm("mov.b64 {%0, %1}, %2;" : "=f"(f.x), "=f"(f.y) : "l"(v)); return f;
}
__device__ __forceinline__ float hsum2(u64t v) { float2 f = funpack2(v); return f.x + f.y; }

// ---------------- fast transcendentals (MUFU; err ~1e-7, budget 1e-3) ------
__device__ __forceinline__ float fast_ex2(float x) {
    float y; asm("ex2.approx.f32 %0, %1;" : "=f"(y) : "f"(x)); return y;
}
__device__ __forceinline__ float fast_rcp(float x) {
    float y; asm("rcp.approx.f32 %0, %1;" : "=f"(y) : "f"(x)); return y;
}
__device__ __forceinline__ float fast_sigmoid(float v) {      // 1/(1+e^-v)
    return fast_rcp(1.f + fast_ex2(-1.4426950408889634f * v));
}
__device__ __forceinline__ float fast_tanh(float v) {         // 2*sigm(2v)-1
    return 2.f * fast_rcp(1.f + fast_ex2(-2.8853900817779268f * v)) - 1.f;
}

// ---------------- scratch (device globals; no allocations allowed) ----------
__device__ float g_gi[(size_t)BSZ * NS_MAX * 192];
__device__ float g_cs[(size_t)BSZ * NS_MAX * 32];
__device__ float g_y [(size_t)BSZ * NF_MAX * 32];

// =====================================================================
// Kernel A (R2 form, known good): gi[b][s][j] = b_ih[j] + W_ih[j,:].x[...]
// =====================================================================
__global__ void __launch_bounds__(128) gi_kernel(const float* __restrict__ x,
                                                 const float* __restrict__ W_ih,
                                                 const float* __restrict__ b_ih,
                                                 int T, int Ns) {
    __shared__ __align__(16) float Wc[32 * 96];     // 12.3 KB
    __shared__ float tile[32 * 129];                // 16.5 KB
    __shared__ float bsh[192];

    const int b   = blockIdx.y;
    const int s0  = blockIdx.x * 128;
    const int tid = threadIdx.x;
    const int s   = s0 + tid;
    const bool valid = (s < Ns);

    for (int i = tid; i < 192; i += 128) bsh[i] = b_ih[i];

    u64t f2[48];
    if (valid) {
        const ulonglong2* xp = reinterpret_cast<const ulonglong2*>(x + (size_t)b * T + (size_t)s * 48);
        #pragma unroll
        for (int q = 0; q < 24; q++) { ulonglong2 v = xp[q]; f2[2*q] = v.x; f2[2*q+1] = v.y; }
    } else {
        #pragma unroll
        for (int i = 0; i < 48; i++) f2[i] = 0ULL;
    }

    int nv = Ns - s0; if (nv > 128) nv = 128;

    for (int jc = 0; jc < 6; jc++) {
        __syncthreads();
        const float* wsrc = W_ih + jc * 32 * 96;
        for (int i = tid; i < 32 * 96; i += 128) Wc[i] = wsrc[i];
        __syncthreads();

        #pragma unroll 1
        for (int jj = 0; jj < 32; jj++) {
            const ulonglong2* wv = reinterpret_cast<const ulonglong2*>(&Wc[jj * 96]);
            u64t a0 = 0ULL, a1 = 0ULL, a2 = 0ULL, a3 = 0ULL;
            #pragma unroll
            for (int p = 0; p < 24; p++) {
                ulonglong2 w = wv[p];
                if (p & 1) { a2 = ffma2(w.x, f2[2*p], a2); a3 = ffma2(w.y, f2[2*p+1], a3); }
                else       { a0 = ffma2(w.x, f2[2*p], a0); a1 = ffma2(w.y, f2[2*p+1], a1); }
            }
            tile[jj * 129 + tid] = hsum2(fadd2(fadd2(a0, a1), fadd2(a2, a3))) + bsh[jc * 32 + jj];
        }
        __syncthreads();

        #pragma unroll
        for (int it = 0; it < 8; it++) {
            int q  = tid + it * 128;
            int j0 = (q & 7) * 4;
            int sl = q >> 3;
            if (sl < nv) {
                float4 v;
                v.x = tile[(j0    ) * 129 + sl];
                v.y = tile[(j0 + 1) * 129 + sl];
                v.z = tile[(j0 + 2) * 129 + sl];
                v.w = tile[(j0 + 3) * 129 + sl];
                *reinterpret_cast<float4*>(&g_gi[((size_t)b * Ns + s0 + sl) * 192 + jc * 32 + j0]) = v;
            }
        }
    }
}

// =====================================================================
// Kernel B v2: GRU recurrence, thread-owns-hidden-unit form.
// 96 threads: j<64 -> unit j owns ALL THREE gate rows (W_hh rows j, j+64,
// j+128 register-resident, 96 FFMA2/step) and does the gate math locally
// in registers (no gh/gi shared traffic). Threads 64..95 -> fused c_s.
// h double-buffered in shared -> ONE barrier per step.
// gi loaded straight to registers, static depth-2 prefetch.
// =====================================================================
__global__ void __launch_bounds__(96, 1) gru_kernel(const float* __restrict__ W_hh,
                                                    const float* __restrict__ b_hh,
                                                    const float* __restrict__ W_cs,
                                                    const float* __restrict__ b_cs,
                                                    int Ns) {
    __shared__ __align__(16) float h_sh[2][64];

    const int b   = blockIdx.x;
    const int tid = threadIdx.x;
    const bool is_gate = (tid < 64);
    const int j = is_gate ? tid : (tid - 64);

    u64t wrr[32], wrz[32], wrn[32];
    float bhr = 0.f, bhz = 0.f, bhn = 0.f, bcs = 0.f;
    if (is_gate) {
        const ulonglong2* r0 = reinterpret_cast<const ulonglong2*>(W_hh + (j      ) * 64);
        const ulonglong2* r1 = reinterpret_cast<const ulonglong2*>(W_hh + (j + 64 ) * 64);
        const ulonglong2* r2 = reinterpret_cast<const ulonglong2*>(W_hh + (j + 128) * 64);
        #pragma unroll
        for (int p = 0; p < 16; p++) {
            ulonglong2 a = r0[p]; wrr[2*p] = a.x; wrr[2*p+1] = a.y;
            ulonglong2 c = r1[p]; wrz[2*p] = c.x; wrz[2*p+1] = c.y;
            ulonglong2 d = r2[p]; wrn[2*p] = d.x; wrn[2*p+1] = d.y;
        }
        bhr = b_hh[j]; bhz = b_hh[j + 64]; bhn = b_hh[j + 128];
    } else {
        const ulonglong2* r0 = reinterpret_cast<const ulonglong2*>(W_cs + j * 64);
        #pragma unroll
        for (int p = 0; p < 16; p++) { ulonglong2 a = r0[p]; wrr[2*p] = a.x; wrr[2*p+1] = a.y; }
        bcs = b_cs[j];
    }

    if (tid < 64) { h_sh[0][tid] = 0.f; }
    __syncthreads();

    const float* gib = g_gi + (size_t)b * Ns * 192;
    float*       csb = g_cs + (size_t)b * Ns * 32;

    // static depth-2 gi prefetch (register-resident, no dynamic indexing)
    float g0r = 0.f, g0z = 0.f, g0n = 0.f, g1r = 0.f, g1z = 0.f, g1n = 0.f;
    if (is_gate) {
        g0r = __ldg(&gib[j]); g0z = __ldg(&gib[j + 64]); g0n = __ldg(&gib[j + 128]);
        if (Ns > 1) {
            g1r = __ldg(&gib[192 + j]); g1z = __ldg(&gib[192 + j + 64]); g1n = __ldg(&gib[192 + j + 128]);
        }
    }

    int p = 0;
    for (int t = 0; t < Ns; t++) {
        const ulonglong2* hv = reinterpret_cast<const ulonglong2*>(h_sh[p]);
        if (is_gate) {
            u64t ar0=0ULL, ar1=0ULL, az0=0ULL, az1=0ULL, an0=0ULL, an1=0ULL;
            #pragma unroll
            for (int q = 0; q < 16; q++) {
                ulonglong2 h4 = hv[q];
                ar0 = ffma2(wrr[2*q], h4.x, ar0); ar1 = ffma2(wrr[2*q+1], h4.y, ar1);
                az0 = ffma2(wrz[2*q], h4.x, az0); az1 = ffma2(wrz[2*q+1], h4.y, az1);
                an0 = ffma2(wrn[2*q], h4.x, an0); an1 = ffma2(wrn[2*q+1], h4.y, an1);
            }
            const float r  = fast_sigmoid(g0r + bhr + hsum2(fadd2(ar0, ar1)));
            const float z  = fast_sigmoid(g0z + bhz + hsum2(fadd2(az0, az1)));
            const float n  = fast_tanh   (g0n + (r * (bhn + hsum2(fadd2(an0, an1)))));
            const float hn = (1.f - z) * n + z * h_sh[p][j];
            h_sh[p ^ 1][j] = hn;

            // rotate prefetch
            g0r = g1r; g0z = g1z; g0n = g1n;
            const int tp = t + 2;
            if (tp < Ns) {
                g1r = __ldg(&gib[tp * 192 + j]);
                g1z = __ldg(&gib[tp * 192 + j + 64]);
                g1n = __ldg(&gib[tp * 192 + j + 128]);
            }
        } else {
            // c_s[t-1] = W_cs . hs[t-1]  (h_sh[p] holds hs[t-1])
            u64t a0 = 0ULL, a1 = 0ULL;
            #pragma unroll
            for (int q = 0; q < 16; q++) {
                ulonglong2 h4 = hv[q];
                a0 = ffma2(wrr[2*q], h4.x, a0); a1 = ffma2(wrr[2*q+1], h4.y, a1);
            }
            if (t > 0) csb[(size_t)(t - 1) * 32 + j] = hsum2(fadd2(a0, a1)) + bcs;
        }
        __syncthreads();
        p ^= 1;
    }

    // final c_s[Ns-1] from hs[Ns-1] (now in h_sh[p])
    if (!is_gate) {
        const ulonglong2* hv = reinterpret_cast<const ulonglong2*>(h_sh[p]);
        u64t a0 = 0ULL, a1 = 0ULL;
        #pragma unroll
        for (int q = 0; q < 16; q++) {
            ulonglong2 h4 = hv[q];
            a0 = ffma2(wrr[2*q], h4.x, a0); a1 = ffma2(wrr[2*q+1], h4.y, a1);
        }
        csb[(size_t)(Ns - 1) * 32 + j] = hsum2(fadd2(a0, a1)) + bcs;
    }
}

// =====================================================================
// Kernel C (R4 form, verified): fast path, 2 consecutive frames per thread.
// =====================================================================
__global__ void __launch_bounds__(128) fast_kernel(const float* __restrict__ x,
                                                   const float* __restrict__ W1,
                                                   const float* __restrict__ b1,
                                                   const float* __restrict__ W2,
                                                   const float* __restrict__ b2,
                                                   int T, int Nf, int Ns) {
    __shared__ __align__(16) float W1sh[64 * 64];   // [j][k]
    __shared__ __align__(16) float W2T[64 * 32];    // [j][i]
    __shared__ float b1sh[64];
    __shared__ u64t  b2sh[16];

    const int b   = blockIdx.y;
    const int tid = threadIdx.x;
    const int n0  = (blockIdx.x * 128 + tid) * 2;
    const int n1  = n0 + 1;

    for (int i = tid; i < 4096; i += 128) W1sh[i] = W1[i];
    for (int i = tid; i < 2048; i += 128) { int jj = i >> 5, ii = i & 31; W2T[i] = W2[ii * 64 + jj]; }
    if (tid < 64) b1sh[tid] = b1[tid];
    if (tid < 16) b2sh[tid] = fpack2(b2[2 * tid], b2[2 * tid + 1]);
    __syncthreads();

    if (n0 >= Nf) return;
    const bool v1 = (n1 < Nf);

    u64t xf[24];
    {
        const float4* xp = reinterpret_cast<const float4*>(x + (size_t)b * T + (size_t)n0 * 16);
        #pragma unroll
        for (int q = 0; q < 12; q++) {
            float4 v = (q < 8 || v1) ? xp[q] : make_float4(0.f, 0.f, 0.f, 0.f);
            xf[2*q]   = fpack2(v.x, v.y);
            xf[2*q+1] = fpack2(v.z, v.w);
        }
    }
    u64t cf0[16], cf1[16];
    {
        int cn0 = n0 / 3 - 1; if (cn0 < 0) cn0 = 0;
        int cn1 = v1 ? (n1 / 3 - 1) : cn0; if (cn1 < 0) cn1 = 0;
        const ulonglong2* cp0 = reinterpret_cast<const ulonglong2*>(g_cs + ((size_t)b * Ns + cn0) * 32);
        const ulonglong2* cp1 = reinterpret_cast<const ulonglong2*>(g_cs + ((size_t)b * Ns + cn1) * 32);
        #pragma unroll
        for (int q = 0; q < 8; q++) {
            ulonglong2 u = cp0[q]; cf0[2*q] = u.x; cf0[2*q+1] = u.y;
            ulonglong2 w = cp1[q]; cf1[2*q] = w.x; cf1[2*q+1] = w.y;
        }
    }

    u64t ya[16], yb[16];
    #pragma unroll
    for (int i = 0; i < 16; i++) { ya[i] = 0ULL; yb[i] = 0ULL; }

    #pragma unroll 1
    for (int jj = 0; jj < 64; jj++) {
        const ulonglong2* w1v = reinterpret_cast<const ulonglong2*>(&W1sh[jj * 64]);
        u64t a0=0ULL,a1=0ULL,a2=0ULL,a3=0ULL;
        u64t c0=0ULL,c1=0ULL,c2=0ULL,c3=0ULL;
        #pragma unroll
        for (int p = 0; p < 8; p++) {
            ulonglong2 w = w1v[p];
            a0 = ffma2(w.x, xf[2*p],   a0); a1 = ffma2(w.y, xf[2*p+1],   a1);
            c0 = ffma2(w.x, xf[8+2*p], c0); c1 = ffma2(w.y, xf[8+2*p+1], c1);
        }
        #pragma unroll
        for (int p = 0; p < 8; p++) {
            ulonglong2 w = w1v[8 + p];
            a2 = ffma2(w.x, cf0[2*p], a2); a3 = ffma2(w.y, cf0[2*p+1], a3);
            c2 = ffma2(w.x, cf1[2*p], c2); c3 = ffma2(w.y, cf1[2*p+1], c3);
        }
        float hA = fmaxf(hsum2(fadd2(fadd2(a0,a1), fadd2(a2,a3))) + b1sh[jj], 0.f);
        float hB = fmaxf(hsum2(fadd2(fadd2(c0,c1), fadd2(c2,c3))) + b1sh[jj], 0.f);
        u64t hA2 = fpack2(hA, hA);
        u64t hB2 = fpack2(hB, hB);
        const ulonglong2* w2v = reinterpret_cast<const ulonglong2*>(&W2T[jj * 32]);
        #pragma unroll
        for (int p = 0; p < 8; p++) {
            ulonglong2 w = w2v[p];
            ya[2*p] = ffma2(w.x, hA2, ya[2*p]); ya[2*p+1] = ffma2(w.y, hA2, ya[2*p+1]);
            yb[2*p] = ffma2(w.x, hB2, yb[2*p]); yb[2*p+1] = ffma2(w.y, hB2, yb[2*p+1]);
        }
    }

    {
        float4* yo = reinterpret_cast<float4*>(&g_y[((size_t)b * Nf + n0) * 32]);
        #pragma unroll
        for (int p = 0; p < 8; p++) {
            float2 va = funpack2(fadd2(ya[2*p],     b2sh[2*p]));
            float2 vb = funpack2(fadd2(ya[2*p + 1], b2sh[2*p + 1]));
            yo[p] = make_float4(va.x, va.y, vb.x, vb.y);
        }
        if (v1) {
            float4* yo1 = reinterpret_cast<float4*>(&g_y[((size_t)b * Nf + n1) * 32]);
            #pragma unroll
            for (int p = 0; p < 8; p++) {
                float2 va = funpack2(fadd2(yb[2*p],     b2sh[2*p]));
                float2 vb = funpack2(fadd2(yb[2*p + 1], b2sh[2*p + 1]));
                yo1[p] = make_float4(va.x, va.y, vb.x, vb.y);
            }
        }
    }
}

// =====================================================================
// Kernel D: overlap-add as gather (each sample covered by <=2 frames).
// =====================================================================
__global__ void __launch_bounds__(256) gather_kernel(float* __restrict__ out,
                                                     int T, int Nf) {
    const int idx = blockIdx.x * blockDim.x + threadIdx.x;
    const int total = BSZ * T;
    if (idx >= total) return;
    const int b = idx / T, t = idx % T;
    const int n0 = t >> 4, r = t & 15;
    const float* yb = g_y + (size_t)b * Nf * 32;
    float v = 0.f;
    if (n0 < Nf)                 v += yb[n0 * 32 + r];
    if (n0 >= 1 && n0 - 1 < Nf)  v += yb[(n0 - 1) * 32 + 16 + r];
    out[idx] = v;
}

// =====================================================================
extern "C" void kernel_launch(void* const* d_in, const int* in_sizes, int n_in,
                              void* d_out, int out_size) {
    const float* x    = (const float*)d_in[0];
    const float* W_ih = (const float*)d_in[1];
    const float* W_hh = (const float*)d_in[2];
    const float* b_ih = (const float*)d_in[3];
    const float* b_hh = (const float*)d_in[4];
    const float* W_cs = (const float*)d_in[5];
    const float* b_cs = (const float*)d_in[6];
    const float* W1   = (const float*)d_in[7];
    const float* b1   = (const float*)d_in[8];
    const float* W2   = (const float*)d_in[9];
    const float* b2   = (const float*)d_in[10];
    float* out = (float*)d_out;

    const int T  = in_sizes[0] / BSZ;
    const int Nf = (T - 32) / 16 + 1;
    const int Ns = (T - 96) / 48 + 1;

    gi_kernel    <<<dim3((Ns + 127) / 128, BSZ), 128>>>(x, W_ih, b_ih, T, Ns);
    gru_kernel   <<<BSZ, 96>>>(W_hh, b_hh, W_cs, b_cs, Ns);
    fast_kernel  <<<dim3((Nf + 255) / 256, BSZ), 128>>>(x, W1, b1, W2, b2, T, Nf, Ns);
    gather_kernel<<<(BSZ * T + 255) / 256, 256>>>(out, T, Nf);
}

// round 10
// speedup vs baseline: 1.2888x; 1.2888x over previous
#include <cuda_runtime.h>
#include <cuda_bf16.h>
#include <cstdint>

// Shapes fixed by dataset: L_F=32, HOP=16, DELTA=3, L_S=96, COND=32, GH=64, B=128, T=48000
// Nf = 2999, Ns = 999
#define BSZ    128
#define NS_MAX 999
#define NF_MAX 2999

typedef unsigned long long u64t;

// ---------------- packed f32x2 helpers (sm_103a FFMA2 path) ----------------
__device__ __forceinline__ u64t ffma2(u64t a, u64t b, u64t c) {
    u64t d; asm("fma.rn.f32x2 %0, %1, %2, %3;" : "=l"(d) : "l"(a), "l"(b), "l"(c)); return d;
}
__device__ __forceinline__ u64t fadd2(u64t a, u64t b) {
    u64t d; asm("add.rn.f32x2 %0, %1, %2;" : "=l"(d) : "l"(a), "l"(b)); return d;
}
__device__ __forceinline__ u64t fpack2(float lo, float hi) {
    u64t d; asm("mov.b64 %0, {%1, %2};" : "=l"(d) : "f"(lo), "f"(hi)); return d;
}
__device__ __forceinline__ float2 funpack2(u64t v) {
    float2 f; asm("mov.b64 {%0, %1}, %2;" : "=f"(f.x), "=f"(f.y) : "l"(v)); return f;
}
__device__ __forceinline__ float hsum2(u64t v) { float2 f = funpack2(v); return f.x + f.y; }

// ---------------- fast transcendentals (MUFU; err ~1e-7, budget 1e-3) ------
__device__ __forceinline__ float fast_ex2(float x) {
    float y; asm("ex2.approx.f32 %0, %1;" : "=f"(y) : "f"(x)); return y;
}
__device__ __forceinline__ float fast_rcp(float x) {
    float y; asm("rcp.approx.f32 %0, %1;" : "=f"(y) : "f"(x)); return y;
}
__device__ __forceinline__ float fast_sigmoid(float v) {      // 1/(1+e^-v)
    return fast_rcp(1.f + fast_ex2(-1.4426950408889634f * v));
}
__device__ __forceinline__ float fast_tanh(float v) {         // 2*sigm(2v)-1
    return 2.f * fast_rcp(1.f + fast_ex2(-2.8853900817779268f * v)) - 1.f;
}

// ---------------- scratch (device globals; no allocations allowed) ----------
__device__ float g_gi[(size_t)BSZ * NS_MAX * 192];
__device__ float g_cs[(size_t)BSZ * NS_MAX * 32];
__device__ float g_y [(size_t)BSZ * NF_MAX * 32];

// =====================================================================
// Kernel A (R2 form, known good): gi[b][s][j] = b_ih[j] + W_ih[j,:].x[...]
// =====================================================================
__global__ void __launch_bounds__(128) gi_kernel(const float* __restrict__ x,
                                                 const float* __restrict__ W_ih,
                                                 const float* __restrict__ b_ih,
                                                 int T, int Ns) {
    __shared__ __align__(16) float Wc[32 * 96];     // 12.3 KB
    __shared__ float tile[32 * 129];                // 16.5 KB
    __shared__ float bsh[192];

    const int b   = blockIdx.y;
    const int s0  = blockIdx.x * 128;
    const int tid = threadIdx.x;
    const int s   = s0 + tid;
    const bool valid = (s < Ns);

    for (int i = tid; i < 192; i += 128) bsh[i] = b_ih[i];

    u64t f2[48];
    if (valid) {
        const ulonglong2* xp = reinterpret_cast<const ulonglong2*>(x + (size_t)b * T + (size_t)s * 48);
        #pragma unroll
        for (int q = 0; q < 24; q++) { ulonglong2 v = xp[q]; f2[2*q] = v.x; f2[2*q+1] = v.y; }
    } else {
        #pragma unroll
        for (int i = 0; i < 48; i++) f2[i] = 0ULL;
    }

    int nv = Ns - s0; if (nv > 128) nv = 128;

    for (int jc = 0; jc < 6; jc++) {
        __syncthreads();
        const float* wsrc = W_ih + jc * 32 * 96;
        for (int i = tid; i < 32 * 96; i += 128) Wc[i] = wsrc[i];
        __syncthreads();

        #pragma unroll 1
        for (int jj = 0; jj < 32; jj++) {
            const ulonglong2* wv = reinterpret_cast<const ulonglong2*>(&Wc[jj * 96]);
            u64t a0 = 0ULL, a1 = 0ULL, a2 = 0ULL, a3 = 0ULL;
            #pragma unroll
            for (int p = 0; p < 24; p++) {
                ulonglong2 w = wv[p];
                if (p & 1) { a2 = ffma2(w.x, f2[2*p], a2); a3 = ffma2(w.y, f2[2*p+1], a3); }
                else       { a0 = ffma2(w.x, f2[2*p], a0); a1 = ffma2(w.y, f2[2*p+1], a1); }
            }
            tile[jj * 129 + tid] = hsum2(fadd2(fadd2(a0, a1), fadd2(a2, a3))) + bsh[jc * 32 + jj];
        }
        __syncthreads();

        #pragma unroll
        for (int it = 0; it < 8; it++) {
            int q  = tid + it * 128;
            int j0 = (q & 7) * 4;
            int sl = q >> 3;
            if (sl < nv) {
                float4 v;
                v.x = tile[(j0    ) * 129 + sl];
                v.y = tile[(j0 + 1) * 129 + sl];
                v.z = tile[(j0 + 2) * 129 + sl];
                v.w = tile[(j0 + 3) * 129 + sl];
                *reinterpret_cast<float4*>(&g_gi[((size_t)b * Ns + s0 + sl) * 192 + jc * 32 + j0]) = v;
            }
        }
    }
}

// =====================================================================
// Kernel B (844us form + depth-4 STATIC prefetch): GRU with fused c_s.
// 224 threads: j<192 -> gate row j (W_hh register-resident, 32 u64);
//              j>=192 -> c_s row j-192, overlapped with the dot phase.
// gi stream prefetched via 4 statically-rotated registers (no dynamic
// indexing -> no spills; covers ~4 step-latencies of DRAM).
// =====================================================================
__global__ void __launch_bounds__(224, 1) gru_kernel(const float* __restrict__ W_hh,
                                                     const float* __restrict__ b_hh,
                                                     const float* __restrict__ W_cs,
                                                     const float* __restrict__ b_cs,
                                                     int Ns) {
    __shared__ __align__(16) float h_sh[64];
    __shared__ float gh_sh[192];
    __shared__ float gi_sh[192];

    const int b = blockIdx.x;
    const int j = threadIdx.x;
    const bool is_gate = (j < 192);

    u64t wr[32];
    float bj;
    {
        const float* wsrc_f = is_gate ? (W_hh + j * 64) : (W_cs + (j - 192) * 64);
        const ulonglong2* wsrc = reinterpret_cast<const ulonglong2*>(wsrc_f);
        #pragma unroll
        for (int p = 0; p < 16; p++) { ulonglong2 v = wsrc[p]; wr[2*p] = v.x; wr[2*p+1] = v.y; }
        bj = is_gate ? b_hh[j] : b_cs[j - 192];
    }
    if (j < 64) h_sh[j] = 0.f;
    __syncthreads();

    const float* gib = g_gi + (size_t)b * Ns * 192;
    float*       csb = g_cs + (size_t)b * Ns * 32;

    // depth-4 static register prefetch ring (explicit rotation, no indexing)
    float g0 = 0.f, g1 = 0.f, g2 = 0.f, g3 = 0.f;
    if (is_gate) {
        g0 = __ldg(&gib[j]);
        if (Ns > 1) g1 = __ldg(&gib[1 * 192 + j]);
        if (Ns > 2) g2 = __ldg(&gib[2 * 192 + j]);
        if (Ns > 3) g3 = __ldg(&gib[3 * 192 + j]);
    }

    for (int t = 0; t < Ns; t++) {
        const float gv = g0;
        g0 = g1; g1 = g2; g2 = g3;
        const int tp = t + 4;
        if (is_gate && tp < Ns) g3 = __ldg(&gib[tp * 192 + j]);   // issued early, 4-step cover

        // dot over h_sh (= hs[t-1])
        const ulonglong2* hv = reinterpret_cast<const ulonglong2*>(h_sh);
        u64t a0 = 0ULL, a1 = 0ULL, a2 = 0ULL, a3 = 0ULL;
        #pragma unroll
        for (int p = 0; p < 16; p++) {
            ulonglong2 h4 = hv[p];
            if (p & 1) { a2 = ffma2(wr[2*p], h4.x, a2); a3 = ffma2(wr[2*p+1], h4.y, a3); }
            else       { a0 = ffma2(wr[2*p], h4.x, a0); a1 = ffma2(wr[2*p+1], h4.y, a1); }
        }
        const float acc = hsum2(fadd2(fadd2(a0, a1), fadd2(a2, a3))) + bj;

        if (is_gate) { gh_sh[j] = acc; gi_sh[j] = gv; }
        else if (t > 0) csb[(size_t)(t - 1) * 32 + (j - 192)] = acc;   // c_s[t-1]
        __syncthreads();

        if (j < 64) {
            const float r  = fast_sigmoid(gi_sh[j]       + gh_sh[j]      );
            const float z  = fast_sigmoid(gi_sh[j + 64]  + gh_sh[j + 64] );
            const float n  = fast_tanh   (gi_sh[j + 128] + r * gh_sh[j + 128]);
            h_sh[j] = (1.f - z) * n + z * h_sh[j];
        }
        __syncthreads();
    }

    // final c_s[Ns-1] on hs[Ns-1]
    if (!is_gate) {
        const ulonglong2* hv = reinterpret_cast<const ulonglong2*>(h_sh);
        u64t a0 = 0ULL, a1 = 0ULL, a2 = 0ULL, a3 = 0ULL;
        #pragma unroll
        for (int p = 0; p < 16; p++) {
            ulonglong2 h4 = hv[p];
            if (p & 1) { a2 = ffma2(wr[2*p], h4.x, a2); a3 = ffma2(wr[2*p+1], h4.y, a3); }
            else       { a0 = ffma2(wr[2*p], h4.x, a0); a1 = ffma2(wr[2*p+1], h4.y, a1); }
        }
        csb[(size_t)(Ns - 1) * 32 + (j - 192)] =
            hsum2(fadd2(fadd2(a0, a1), fadd2(a2, a3))) + bj;
    }
}

// =====================================================================
// Kernel C (R4 form, verified 144us): fast path, 2 consecutive frames per
// thread (share 16 x-samples). Per jj: 24 broadcast LDS.128 feed 96 FFMA2.
// =====================================================================
__global__ void __launch_bounds__(128) fast_kernel(const float* __restrict__ x,
                                                   const float* __restrict__ W1,
                                                   const float* __restrict__ b1,
                                                   const float* __restrict__ W2,
                                                   const float* __restrict__ b2,
                                                   int T, int Nf, int Ns) {
    __shared__ __align__(16) float W1sh[64 * 64];   // [j][k]
    __shared__ __align__(16) float W2T[64 * 32];    // [j][i]
    __shared__ float b1sh[64];
    __shared__ u64t  b2sh[16];

    const int b   = blockIdx.y;
    const int tid = threadIdx.x;
    const int n0  = (blockIdx.x * 128 + tid) * 2;
    const int n1  = n0 + 1;

    for (int i = tid; i < 4096; i += 128) W1sh[i] = W1[i];
    for (int i = tid; i < 2048; i += 128) { int jj = i >> 5, ii = i & 31; W2T[i] = W2[ii * 64 + jj]; }
    if (tid < 64) b1sh[tid] = b1[tid];
    if (tid < 16) b2sh[tid] = fpack2(b2[2 * tid], b2[2 * tid + 1]);
    __syncthreads();

    if (n0 >= Nf) return;
    const bool v1 = (n1 < Nf);

    u64t xf[24];
    {
        const float4* xp = reinterpret_cast<const float4*>(x + (size_t)b * T + (size_t)n0 * 16);
        #pragma unroll
        for (int q = 0; q < 12; q++) {
            float4 v = (q < 8 || v1) ? xp[q] : make_float4(0.f, 0.f, 0.f, 0.f);
            xf[2*q]   = fpack2(v.x, v.y);
            xf[2*q+1] = fpack2(v.z, v.w);
        }
    }
    u64t cf0[16], cf1[16];
    {
        int cn0 = n0 / 3 - 1; if (cn0 < 0) cn0 = 0;
        int cn1 = v1 ? (n1 / 3 - 1) : cn0; if (cn1 < 0) cn1 = 0;
        const ulonglong2* cp0 = reinterpret_cast<const ulonglong2*>(g_cs + ((size_t)b * Ns + cn0) * 32);
        const ulonglong2* cp1 = reinterpret_cast<const ulonglong2*>(g_cs + ((size_t)b * Ns + cn1) * 32);
        #pragma unroll
        for (int q = 0; q < 8; q++) {
            ulonglong2 u = cp0[q]; cf0[2*q] = u.x; cf0[2*q+1] = u.y;
            ulonglong2 w = cp1[q]; cf1[2*q] = w.x; cf1[2*q+1] = w.y;
        }
    }

    u64t ya[16], yb[16];
    #pragma unroll
    for (int i = 0; i < 16; i++) { ya[i] = 0ULL; yb[i] = 0ULL; }

    #pragma unroll 1
    for (int jj = 0; jj < 64; jj++) {
        const ulonglong2* w1v = reinterpret_cast<const ulonglong2*>(&W1sh[jj * 64]);
        u64t a0=0ULL,a1=0ULL,a2=0ULL,a3=0ULL;
        u64t c0=0ULL,c1=0ULL,c2=0ULL,c3=0ULL;
        #pragma unroll
        for (int p = 0; p < 8; p++) {
            ulonglong2 w = w1v[p];
            a0 = ffma2(w.x, xf[2*p],   a0); a1 = ffma2(w.y, xf[2*p+1],   a1);
            c0 = ffma2(w.x, xf[8+2*p], c0); c1 = ffma2(w.y, xf[8+2*p+1], c1);
        }
        #pragma unroll
        for (int p = 0; p < 8; p++) {
            ulonglong2 w = w1v[8 + p];
            a2 = ffma2(w.x, cf0[2*p], a2); a3 = ffma2(w.y, cf0[2*p+1], a3);
            c2 = ffma2(w.x, cf1[2*p], c2); c3 = ffma2(w.y, cf1[2*p+1], c3);
        }
        float hA = fmaxf(hsum2(fadd2(fadd2(a0,a1), fadd2(a2,a3))) + b1sh[jj], 0.f);
        float hB = fmaxf(hsum2(fadd2(fadd2(c0,c1), fadd2(c2,c3))) + b1sh[jj], 0.f);
        u64t hA2 = fpack2(hA, hA);
        u64t hB2 = fpack2(hB, hB);
        const ulonglong2* w2v = reinterpret_cast<const ulonglong2*>(&W2T[jj * 32]);
        #pragma unroll
        for (int p = 0; p < 8; p++) {
            ulonglong2 w = w2v[p];
            ya[2*p] = ffma2(w.x, hA2, ya[2*p]); ya[2*p+1] = ffma2(w.y, hA2, ya[2*p+1]);
            yb[2*p] = ffma2(w.x, hB2, yb[2*p]); yb[2*p+1] = ffma2(w.y, hB2, yb[2*p+1]);
        }
    }

    {
        float4* yo = reinterpret_cast<float4*>(&g_y[((size_t)b * Nf + n0) * 32]);
        #pragma unroll
        for (int p = 0; p < 8; p++) {
            float2 va = funpack2(fadd2(ya[2*p],     b2sh[2*p]));
            float2 vb = funpack2(fadd2(ya[2*p + 1], b2sh[2*p + 1]));
            yo[p] = make_float4(va.x, va.y, vb.x, vb.y);
        }
        if (v1) {
            float4* yo1 = reinterpret_cast<float4*>(&g_y[((size_t)b * Nf + n1) * 32]);
            #pragma unroll
            for (int p = 0; p < 8; p++) {
                float2 va = funpack2(fadd2(yb[2*p],     b2sh[2*p]));
                float2 vb = funpack2(fadd2(yb[2*p + 1], b2sh[2*p + 1]));
                yo1[p] = make_float4(va.x, va.y, vb.x, vb.y);
            }
        }
    }
}

// =====================================================================
// Kernel D: overlap-add as gather (each sample covered by <=2 frames).
// =====================================================================
__global__ void __launch_bounds__(256) gather_kernel(float* __restrict__ out,
                                                     int T, int Nf) {
    const int idx = blockIdx.x * blockDim.x + threadIdx.x;
    const int total = BSZ * T;
    if (idx >= total) return;
    const int b = idx / T, t = idx % T;
    const int n0 = t >> 4, r = t & 15;
    const float* yb = g_y + (size_t)b * Nf * 32;
    float v = 0.f;
    if (n0 < Nf)                 v += yb[n0 * 32 + r];
    if (n0 >= 1 && n0 - 1 < Nf)  v += yb[(n0 - 1) * 32 + 16 + r];
    out[idx] = v;
}

// =====================================================================
extern "C" void kernel_launch(void* const* d_in, const int* in_sizes, int n_in,
                              void* d_out, int out_size) {
    const float* x    = (const float*)d_in[0];
    const float* W_ih = (const float*)d_in[1];
    const float* W_hh = (const float*)d_in[2];
    const float* b_ih = (const float*)d_in[3];
    const float* b_hh = (const float*)d_in[4];
    const float* W_cs = (const float*)d_in[5];
    const float* b_cs = (const float*)d_in[6];
    const float* W1   = (const float*)d_in[7];
    const float* b1   = (const float*)d_in[8];
    const float* W2   = (const float*)d_in[9];
    const float* b2   = (const float*)d_in[10];
    float* out = (float*)d_out;

    const int T  = in_sizes[0] / BSZ;
    const int Nf = (T - 32) / 16 + 1;
    const int Ns = (T - 96) / 48 + 1;

    gi_kernel    <<<dim3((Ns + 127) / 128, BSZ), 128>>>(x, W_ih, b_ih, T, Ns);
    gru_kernel   <<<BSZ, 224>>>(W_hh, b_hh, W_cs, b_cs, Ns);
    fast_kernel  <<<dim3((Nf + 255) / 256, BSZ), 128>>>(x, W1, b1, W2, b2, T, Nf, Ns);
    gather_kernel<<<(BSZ * T + 255) / 256, 256>>>(out, T, Nf);
}

// round 11
// speedup vs baseline: 1.3331x; 1.0343x over previous
#include <cuda_runtime.h>
#include <cuda_bf16.h>
#include <cstdint>

// Shapes fixed by dataset: L_F=32, HOP=16, DELTA=3, L_S=96, COND=32, GH=64, B=128, T=48000
// Nf = 2999, Ns = 999
#define BSZ    128
#define NS_MAX 999
#define NF_MAX 2999

typedef unsigned long long u64t;

// ---------------- packed f32x2 helpers (sm_103a FFMA2 path) ----------------
__device__ __forceinline__ u64t ffma2(u64t a, u64t b, u64t c) {
    u64t d; asm("fma.rn.f32x2 %0, %1, %2, %3;" : "=l"(d) : "l"(a), "l"(b), "l"(c)); return d;
}
__device__ __forceinline__ u64t fadd2(u64t a, u64t b) {
    u64t d; asm("add.rn.f32x2 %0, %1, %2;" : "=l"(d) : "l"(a), "l"(b)); return d;
}
__device__ __forceinline__ u64t fpack2(float lo, float hi) {
    u64t d; asm("mov.b64 %0, {%1, %2};" : "=l"(d) : "f"(lo), "f"(hi)); return d;
}
__device__ __forceinline__ float2 funpack2(u64t v) {
    float2 f; asm("mov.b64 {%0, %1}, %2;" : "=f"(f.x), "=f"(f.y) : "l"(v)); return f;
}
__device__ __forceinline__ float hsum2(u64t v) { float2 f = funpack2(v); return f.x + f.y; }

// ---------------- fast transcendentals (MUFU; err ~1e-7, budget 1e-3) ------
__device__ __forceinline__ float fast_ex2(float x) {
    float y; asm("ex2.approx.f32 %0, %1;" : "=f"(y) : "f"(x)); return y;
}
__device__ __forceinline__ float fast_rcp(float x) {
    float y; asm("rcp.approx.f32 %0, %1;" : "=f"(y) : "f"(x)); return y;
}
__device__ __forceinline__ float fast_sigmoid(float v) {
    return fast_rcp(1.f + fast_ex2(-1.4426950408889634f * v));
}
__device__ __forceinline__ float fast_tanh(float v) {
    return 2.f * fast_rcp(1.f + fast_ex2(-2.8853900817779268f * v)) - 1.f;
}

// ---------------- scratch (device globals; no allocations allowed) ----------
__device__ float g_gi  [(size_t)BSZ * NS_MAX * 192];
__device__ float g_cs  [(size_t)BSZ * NS_MAX * 32];
__device__ float g_y   [(size_t)BSZ * NF_MAX * 32];
__device__ float g_WihT[96 * 192];                    // transposed W_ih

// =====================================================================
// Kernel P: one-time transpose W_ihT[k][j] = W_ih[j][k]
// =====================================================================
__global__ void __launch_bounds__(256) prep_kernel(const float* __restrict__ W_ih) {
    for (int idx = threadIdx.x; idx < 192 * 96; idx += 256) {
        int j = idx / 96, k = idx % 96;
        g_WihT[k * 192 + j] = W_ih[idx];
    }
}

// =====================================================================
// Kernel A v4: register-tiled GEMM. gi[b][s][:] = W_ih . x-window + b_ih
// Block: 192 threads = 24 jg x 8 sg; thread tile 8 j x 8 s.
// Per k: 2 LDS.128 (w, j-packed u64 pairs) + 2 LDS.128 (x) -> 32 FFMA2.
// Shared: Wsh[96][192] (from g_WihT, coalesced) + xpadT[96][72].
// =====================================================================
#define GI_STILE 64
#define XST 72
__global__ void __launch_bounds__(192) gi_kernel(const float* __restrict__ x,
                                                 const float* __restrict__ b_ih,
                                                 int T, int Ns) {
    extern __shared__ float smem[];
    float* Wsh   = smem;               // 96*192 = 18432 floats
    float* xpadT = smem + 18432;       // 96*72  =  6912 floats

    const int b   = blockIdx.y;
    const int s0b = blockIdx.x * GI_STILE;
    const int tid = threadIdx.x;
    const int jg  = tid >> 3;          // 0..23  (j0 = jg*8)
    const int sg  = tid & 7;           // 0..7   (s-local = sg*8 + e)

    // stage transposed weights (coalesced float4)
    {
        const float4* wsrc = reinterpret_cast<const float4*>(g_WihT);
        float4*       wdst = reinterpret_cast<float4*>(Wsh);
        for (int i = tid; i < 18432 / 4; i += 192) wdst[i] = wsrc[i];
    }
    // stage x window transposed: xpadT[k][s] = x[b, (s0b+s)*48 + k]
    {
        const float* xb = x + (size_t)b * T;
        for (int idx = tid; idx < 96 * GI_STILE; idx += 192) {
            int s = idx / 96, k = idx % 96;
            int g = (s0b + s) * 48 + k;
            xpadT[k * XST + s] = (g < T) ? xb[g] : 0.f;
        }
    }
    __syncthreads();

    u64t acc[4][8];                    // [jp][e]  j = jg*8 + 2*jp(+1), s = sg*8 + e
    #pragma unroll
    for (int jp = 0; jp < 4; jp++)
        #pragma unroll
        for (int e = 0; e < 8; e++) acc[jp][e] = 0ULL;

    #pragma unroll 4
    for (int k = 0; k < 96; k++) {
        const ulonglong2* wp = reinterpret_cast<const ulonglong2*>(&Wsh[k * 192 + jg * 8]);
        const ulonglong2 w01 = wp[0];  // (w_j0,w_j0+1), (w_j0+2,w_j0+3)
        const ulonglong2 w23 = wp[1];
        const float4 xa = *reinterpret_cast<const float4*>(&xpadT[k * XST + sg * 8]);
        const float4 xb4 = *reinterpret_cast<const float4*>(&xpadT[k * XST + sg * 8 + 4]);
        u64t x2[8];
        x2[0] = fpack2(xa.x, xa.x);  x2[1] = fpack2(xa.y, xa.y);
        x2[2] = fpack2(xa.z, xa.z);  x2[3] = fpack2(xa.w, xa.w);
        x2[4] = fpack2(xb4.x, xb4.x); x2[5] = fpack2(xb4.y, xb4.y);
        x2[6] = fpack2(xb4.z, xb4.z); x2[7] = fpack2(xb4.w, xb4.w);
        #pragma unroll
        for (int e = 0; e < 8; e++) {
            acc[0][e] = ffma2(w01.x, x2[e], acc[0][e]);
            acc[1][e] = ffma2(w01.y, x2[e], acc[1][e]);
            acc[2][e] = ffma2(w23.x, x2[e], acc[2][e]);
            acc[3][e] = ffma2(w23.y, x2[e], acc[3][e]);
        }
    }

    // bias (packed to match jp pairs), then store 2x STG.128 per s
    u64t bb[4];
    #pragma unroll
    for (int jp = 0; jp < 4; jp++)
        bb[jp] = fpack2(__ldg(&b_ih[jg * 8 + 2 * jp]), __ldg(&b_ih[jg * 8 + 2 * jp + 1]));

    #pragma unroll
    for (int e = 0; e < 8; e++) {
        const int s = s0b + sg * 8 + e;
        if (s < Ns) {
            float2 v0 = funpack2(fadd2(acc[0][e], bb[0]));
            float2 v1 = funpack2(fadd2(acc[1][e], bb[1]));
            float2 v2 = funpack2(fadd2(acc[2][e], bb[2]));
            float2 v3 = funpack2(fadd2(acc[3][e], bb[3]));
            float4* o = reinterpret_cast<float4*>(&g_gi[((size_t)b * Ns + s) * 192 + jg * 8]);
            o[0] = make_float4(v0.x, v0.y, v1.x, v1.y);
            o[1] = make_float4(v2.x, v2.y, v3.x, v3.y);
        }
    }
}

// =====================================================================
// Kernel B v4: GRU recurrence, 128 threads (4 warps).
// tid<96: gate threads own TWO rows (tid, tid+96) -> 64 u64 W regs.
// tid>=96: cs warp (W_cs row tid-96), overlapped with dot phase.
// Shared h broadcast cost halved vs 224-thread version.
// =====================================================================
__global__ void __launch_bounds__(128, 1) gru_kernel(const float* __restrict__ W_hh,
                                                     const float* __restrict__ b_hh,
                                                     const float* __restrict__ W_cs,
                                                     const float* __restrict__ b_cs,
                                                     int Ns) {
    __shared__ __align__(16) float h_sh[64];
    __shared__ float gh_sh[192];
    __shared__ float gi_sh[192];

    const int b   = blockIdx.x;
    const int tid = threadIdx.x;
    const bool is_gate = (tid < 96);

    u64t wA[32], wB[32];
    float bA = 0.f, bB = 0.f;
    if (is_gate) {
        const ulonglong2* rA = reinterpret_cast<const ulonglong2*>(W_hh + (size_t)tid * 64);
        const ulonglong2* rB = reinterpret_cast<const ulonglong2*>(W_hh + (size_t)(tid + 96) * 64);
        #pragma unroll
        for (int p = 0; p < 16; p++) {
            ulonglong2 a = rA[p]; wA[2*p] = a.x; wA[2*p+1] = a.y;
            ulonglong2 c = rB[p]; wB[2*p] = c.x; wB[2*p+1] = c.y;
        }
        bA = b_hh[tid]; bB = b_hh[tid + 96];
    } else {
        const ulonglong2* rA = reinterpret_cast<const ulonglong2*>(W_cs + (size_t)(tid - 96) * 64);
        #pragma unroll
        for (int p = 0; p < 16; p++) {
            ulonglong2 a = rA[p]; wA[2*p] = a.x; wA[2*p+1] = a.y;
            wB[2*p] = 0ULL; wB[2*p+1] = 0ULL;
        }
        bA = b_cs[tid - 96];
    }
    if (tid < 64) h_sh[tid] = 0.f;
    __syncthreads();

    const float* gib = g_gi + (size_t)b * Ns * 192;
    float*       csb = g_cs + (size_t)b * Ns * 32;

    float gA = 0.f, gB = 0.f;
    if (is_gate) { gA = __ldg(&gib[tid]); gB = __ldg(&gib[tid + 96]); }

    for (int t = 0; t < Ns; t++) {
        float gAn = 0.f, gBn = 0.f;
        if (is_gate && t + 1 < Ns) {
            gAn = __ldg(&gib[(size_t)(t + 1) * 192 + tid]);
            gBn = __ldg(&gib[(size_t)(t + 1) * 192 + tid + 96]);
        }

        const ulonglong2* hv = reinterpret_cast<const ulonglong2*>(h_sh);
        if (is_gate) {
            u64t a0 = 0ULL, a1 = 0ULL, c0 = 0ULL, c1 = 0ULL;
            #pragma unroll
            for (int p = 0; p < 16; p++) {
                ulonglong2 h4 = hv[p];
                a0 = ffma2(wA[2*p], h4.x, a0); a1 = ffma2(wA[2*p+1], h4.y, a1);
                c0 = ffma2(wB[2*p], h4.x, c0); c1 = ffma2(wB[2*p+1], h4.y, c1);
            }
            gh_sh[tid]      = hsum2(fadd2(a0, a1)) + bA;
            gh_sh[tid + 96] = hsum2(fadd2(c0, c1)) + bB;
            gi_sh[tid]      = gA;
            gi_sh[tid + 96] = gB;
        } else {
            u64t a0 = 0ULL, a1 = 0ULL;
            #pragma unroll
            for (int p = 0; p < 16; p++) {
                ulonglong2 h4 = hv[p];
                a0 = ffma2(wA[2*p], h4.x, a0); a1 = ffma2(wA[2*p+1], h4.y, a1);
            }
            if (t > 0) csb[(size_t)(t - 1) * 32 + (tid - 96)] = hsum2(fadd2(a0, a1)) + bA;
        }
        __syncthreads();

        if (tid < 64) {
            const float r  = fast_sigmoid(gi_sh[tid]       + gh_sh[tid]      );
            const float z  = fast_sigmoid(gi_sh[tid + 64]  + gh_sh[tid + 64] );
            const float n  = fast_tanh   (gi_sh[tid + 128] + r * gh_sh[tid + 128]);
            h_sh[tid] = (1.f - z) * n + z * h_sh[tid];
        }
        __syncthreads();
        gA = gAn; gB = gBn;
    }

    // final c_s[Ns-1] from hs[Ns-1]
    if (!is_gate) {
        const ulonglong2* hv = reinterpret_cast<const ulonglong2*>(h_sh);
        u64t a0 = 0ULL, a1 = 0ULL;
        #pragma unroll
        for (int p = 0; p < 16; p++) {
            ulonglong2 h4 = hv[p];
            a0 = ffma2(wA[2*p], h4.x, a0); a1 = ffma2(wA[2*p+1], h4.y, a1);
        }
        csb[(size_t)(Ns - 1) * 32 + (tid - 96)] = hsum2(fadd2(a0, a1)) + bA;
    }
}

// =====================================================================
// Kernel C (R4 form, verified 144us): fast path, 2 consecutive frames per
// thread (share 16 x-samples).
// =====================================================================
__global__ void __launch_bounds__(128) fast_kernel(const float* __restrict__ x,
                                                   const float* __restrict__ W1,
                                                   const float* __restrict__ b1,
                                                   const float* __restrict__ W2,
                                                   const float* __restrict__ b2,
                                                   int T, int Nf, int Ns) {
    __shared__ __align__(16) float W1sh[64 * 64];
    __shared__ __align__(16) float W2T[64 * 32];
    __shared__ float b1sh[64];
    __shared__ u64t  b2sh[16];

    const int b   = blockIdx.y;
    const int tid = threadIdx.x;
    const int n0  = (blockIdx.x * 128 + tid) * 2;
    const int n1  = n0 + 1;

    for (int i = tid; i < 4096; i += 128) W1sh[i] = W1[i];
    for (int i = tid; i < 2048; i += 128) { int jj = i >> 5, ii = i & 31; W2T[i] = W2[ii * 64 + jj]; }
    if (tid < 64) b1sh[tid] = b1[tid];
    if (tid < 16) b2sh[tid] = fpack2(b2[2 * tid], b2[2 * tid + 1]);
    __syncthreads();

    if (n0 >= Nf) return;
    const bool v1 = (n1 < Nf);

    u64t xf[24];
    {
        const float4* xp = reinterpret_cast<const float4*>(x + (size_t)b * T + (size_t)n0 * 16);
        #pragma unroll
        for (int q = 0; q < 12; q++) {
            float4 v = (q < 8 || v1) ? xp[q] : make_float4(0.f, 0.f, 0.f, 0.f);
            xf[2*q]   = fpack2(v.x, v.y);
            xf[2*q+1] = fpack2(v.z, v.w);
        }
    }
    u64t cf0[16], cf1[16];
    {
        int cn0 = n0 / 3 - 1; if (cn0 < 0) cn0 = 0;
        int cn1 = v1 ? (n1 / 3 - 1) : cn0; if (cn1 < 0) cn1 = 0;
        const ulonglong2* cp0 = reinterpret_cast<const ulonglong2*>(g_cs + ((size_t)b * Ns + cn0) * 32);
        const ulonglong2* cp1 = reinterpret_cast<const ulonglong2*>(g_cs + ((size_t)b * Ns + cn1) * 32);
        #pragma unroll
        for (int q = 0; q < 8; q++) {
            ulonglong2 u = cp0[q]; cf0[2*q] = u.x; cf0[2*q+1] = u.y;
            ulonglong2 w = cp1[q]; cf1[2*q] = w.x; cf1[2*q+1] = w.y;
        }
    }

    u64t ya[16], yb[16];
    #pragma unroll
    for (int i = 0; i < 16; i++) { ya[i] = 0ULL; yb[i] = 0ULL; }

    #pragma unroll 1
    for (int jj = 0; jj < 64; jj++) {
        const ulonglong2* w1v = reinterpret_cast<const ulonglong2*>(&W1sh[jj * 64]);
        u64t a0=0ULL,a1=0ULL,a2=0ULL,a3=0ULL;
        u64t c0=0ULL,c1=0ULL,c2=0ULL,c3=0ULL;
        #pragma unroll
        for (int p = 0; p < 8; p++) {
            ulonglong2 w = w1v[p];
            a0 = ffma2(w.x, xf[2*p],   a0); a1 = ffma2(w.y, xf[2*p+1],   a1);
            c0 = ffma2(w.x, xf[8+2*p], c0); c1 = ffma2(w.y, xf[8+2*p+1], c1);
        }
        #pragma unroll
        for (int p = 0; p < 8; p++) {
            ulonglong2 w = w1v[8 + p];
            a2 = ffma2(w.x, cf0[2*p], a2); a3 = ffma2(w.y, cf0[2*p+1], a3);
            c2 = ffma2(w.x, cf1[2*p], c2); c3 = ffma2(w.y, cf1[2*p+1], c3);
        }
        float hA = fmaxf(hsum2(fadd2(fadd2(a0,a1), fadd2(a2,a3))) + b1sh[jj], 0.f);
        float hB = fmaxf(hsum2(fadd2(fadd2(c0,c1), fadd2(c2,c3))) + b1sh[jj], 0.f);
        u64t hA2 = fpack2(hA, hA);
        u64t hB2 = fpack2(hB, hB);
        const ulonglong2* w2v = reinterpret_cast<const ulonglong2*>(&W2T[jj * 32]);
        #pragma unroll
        for (int p = 0; p < 8; p++) {
            ulonglong2 w = w2v[p];
            ya[2*p] = ffma2(w.x, hA2, ya[2*p]); ya[2*p+1] = ffma2(w.y, hA2, ya[2*p+1]);
            yb[2*p] = ffma2(w.x, hB2, yb[2*p]); yb[2*p+1] = ffma2(w.y, hB2, yb[2*p+1]);
        }
    }

    {
        float4* yo = reinterpret_cast<float4*>(&g_y[((size_t)b * Nf + n0) * 32]);
        #pragma unroll
        for (int p = 0; p < 8; p++) {
            float2 va = funpack2(fadd2(ya[2*p],     b2sh[2*p]));
            float2 vb = funpack2(fadd2(ya[2*p + 1], b2sh[2*p + 1]));
            yo[p] = make_float4(va.x, va.y, vb.x, vb.y);
        }
        if (v1) {
            float4* yo1 = reinterpret_cast<float4*>(&g_y[((size_t)b * Nf + n1) * 32]);
            #pragma unroll
            for (int p = 0; p < 8; p++) {
                float2 va = funpack2(fadd2(yb[2*p],     b2sh[2*p]));
                float2 vb = funpack2(fadd2(yb[2*p + 1], b2sh[2*p + 1]));
                yo1[p] = make_float4(va.x, va.y, vb.x, vb.y);
            }
        }
    }
}

// =====================================================================
// Kernel D: overlap-add as gather (each sample covered by <=2 frames).
// =====================================================================
__global__ void __launch_bounds__(256) gather_kernel(float* __restrict__ out,
                                                     int T, int Nf) {
    const int idx = blockIdx.x * blockDim.x + threadIdx.x;
    const int total = BSZ * T;
    if (idx >= total) return;
    const int b = idx / T, t = idx % T;
    const int n0 = t >> 4, r = t & 15;
    const float* yb = g_y + (size_t)b * Nf * 32;
    float v = 0.f;
    if (n0 < Nf)                 v += yb[n0 * 32 + r];
    if (n0 >= 1 && n0 - 1 < Nf)  v += yb[(n0 - 1) * 32 + 16 + r];
    out[idx] = v;
}

// =====================================================================
extern "C" void kernel_launch(void* const* d_in, const int* in_sizes, int n_in,
                              void* d_out, int out_size) {
    const float* x    = (const float*)d_in[0];
    const float* W_ih = (const float*)d_in[1];
    const float* W_hh = (const float*)d_in[2];
    const float* b_ih = (const float*)d_in[3];
    const float* b_hh = (const float*)d_in[4];
    const float* W_cs = (const float*)d_in[5];
    const float* b_cs = (const float*)d_in[6];
    const float* W1   = (const float*)d_in[7];
    const float* b1   = (const float*)d_in[8];
    const float* W2   = (const float*)d_in[9];
    const float* b2   = (const float*)d_in[10];
    float* out = (float*)d_out;

    const int T  = in_sizes[0] / BSZ;
    const int Nf = (T - 32) / 16 + 1;
    const int Ns = (T - 96) / 48 + 1;

    const int GI_SMEM = (18432 + 96 * XST) * (int)sizeof(float);   // ~101 KB
    cudaFuncSetAttribute(gi_kernel, cudaFuncAttributeMaxDynamicSharedMemorySize, GI_SMEM);

    prep_kernel  <<<1, 256>>>(W_ih);
    gi_kernel    <<<dim3((Ns + GI_STILE - 1) / GI_STILE, BSZ), 192, GI_SMEM>>>(x, b_ih, T, Ns);
    gru_kernel   <<<BSZ, 128>>>(W_hh, b_hh, W_cs, b_cs, Ns);
    fast_kernel  <<<dim3((Nf + 255) / 256, BSZ), 128>>>(x, W1, b1, W2, b2, T, Nf, Ns);
    gather_kernel<<<(BSZ * T + 255) / 256, 256>>>(out, T, Nf);
}

// round 12
// speedup vs baseline: 1.5288x; 1.1468x over previous
#include <cuda_runtime.h>
#include <cuda_bf16.h>
#include <cstdint>

// Shapes fixed by dataset: L_F=32, HOP=16, DELTA=3, L_S=96, COND=32, GH=64, B=128, T=48000
// Nf = 2999, Ns = 999
#define BSZ    128
#define NS_MAX 999
#define NF_MAX 2999

typedef unsigned long long u64t;

// ---------------- packed f32x2 helpers (sm_103a FFMA2 path) ----------------
__device__ __forceinline__ u64t ffma2(u64t a, u64t b, u64t c) {
    u64t d; asm("fma.rn.f32x2 %0, %1, %2, %3;" : "=l"(d) : "l"(a), "l"(b), "l"(c)); return d;
}
__device__ __forceinline__ u64t fadd2(u64t a, u64t b) {
    u64t d; asm("add.rn.f32x2 %0, %1, %2;" : "=l"(d) : "l"(a), "l"(b)); return d;
}
__device__ __forceinline__ u64t fpack2(float lo, float hi) {
    u64t d; asm("mov.b64 %0, {%1, %2};" : "=l"(d) : "f"(lo), "f"(hi)); return d;
}
__device__ __forceinline__ float2 funpack2(u64t v) {
    float2 f; asm("mov.b64 {%0, %1}, %2;" : "=f"(f.x), "=f"(f.y) : "l"(v)); return f;
}
__device__ __forceinline__ float hsum2(u64t v) { float2 f = funpack2(v); return f.x + f.y; }

// ---------------- fast transcendentals (MUFU; err ~1e-7, budget 1e-3) ------
__device__ __forceinline__ float fast_ex2(float x) {
    float y; asm("ex2.approx.f32 %0, %1;" : "=f"(y) : "f"(x)); return y;
}
__device__ __forceinline__ float fast_rcp(float x) {
    float y; asm("rcp.approx.f32 %0, %1;" : "=f"(y) : "f"(x)); return y;
}
__device__ __forceinline__ float fast_sigmoid(float v) {
    return fast_rcp(1.f + fast_ex2(-1.4426950408889634f * v));
}
__device__ __forceinline__ float fast_tanh(float v) {
    return 2.f * fast_rcp(1.f + fast_ex2(-2.8853900817779268f * v)) - 1.f;
}

// ---------------- scratch (device globals; no allocations allowed) ----------
__device__ float g_gi  [(size_t)BSZ * NS_MAX * 192];
__device__ float g_cs  [(size_t)BSZ * NS_MAX * 32];
__device__ float g_y   [(size_t)BSZ * NF_MAX * 32];
__device__ float g_WihT[96 * 192];
__device__ int   g_prog[BSZ];          // c_s progress per batch: c_s[0..p-1] ready

// =====================================================================
// Kernel P: one-time transpose W_ihT[k][j] = W_ih[j][k]; reset progress.
// =====================================================================
__global__ void __launch_bounds__(256) prep_kernel(const float* __restrict__ W_ih) {
    if (threadIdx.x < BSZ) g_prog[threadIdx.x] = 0;
    for (int idx = threadIdx.x; idx < 192 * 96; idx += 256) {
        int j = idx / 96, k = idx % 96;
        g_WihT[k * 192 + j] = W_ih[idx];
    }
}

// =====================================================================
// Kernel A v4 (unchanged from 809us config): register-tiled GEMM.
// =====================================================================
#define GI_STILE 64
#define XST 72
__global__ void __launch_bounds__(192) gi_kernel(const float* __restrict__ x,
                                                 const float* __restrict__ b_ih,
                                                 int T, int Ns) {
    extern __shared__ float smem[];
    float* Wsh   = smem;
    float* xpadT = smem + 18432;

    const int b   = blockIdx.y;
    const int s0b = blockIdx.x * GI_STILE;
    const int tid = threadIdx.x;
    const int jg  = tid >> 3;
    const int sg  = tid & 7;

    {
        const float4* wsrc = reinterpret_cast<const float4*>(g_WihT);
        float4*       wdst = reinterpret_cast<float4*>(Wsh);
        for (int i = tid; i < 18432 / 4; i += 192) wdst[i] = wsrc[i];
    }
    {
        const float* xb = x + (size_t)b * T;
        for (int idx = tid; idx < 96 * GI_STILE; idx += 192) {
            int s = idx / 96, k = idx % 96;
            int g = (s0b + s) * 48 + k;
            xpadT[k * XST + s] = (g < T) ? xb[g] : 0.f;
        }
    }
    __syncthreads();

    u64t acc[4][8];
    #pragma unroll
    for (int jp = 0; jp < 4; jp++)
        #pragma unroll
        for (int e = 0; e < 8; e++) acc[jp][e] = 0ULL;

    #pragma unroll 4
    for (int k = 0; k < 96; k++) {
        const ulonglong2* wp = reinterpret_cast<const ulonglong2*>(&Wsh[k * 192 + jg * 8]);
        const ulonglong2 w01 = wp[0];
        const ulonglong2 w23 = wp[1];
        const float4 xa  = *reinterpret_cast<const float4*>(&xpadT[k * XST + sg * 8]);
        const float4 xb4 = *reinterpret_cast<const float4*>(&xpadT[k * XST + sg * 8 + 4]);
        u64t x2[8];
        x2[0] = fpack2(xa.x, xa.x);   x2[1] = fpack2(xa.y, xa.y);
        x2[2] = fpack2(xa.z, xa.z);   x2[3] = fpack2(xa.w, xa.w);
        x2[4] = fpack2(xb4.x, xb4.x); x2[5] = fpack2(xb4.y, xb4.y);
        x2[6] = fpack2(xb4.z, xb4.z); x2[7] = fpack2(xb4.w, xb4.w);
        #pragma unroll
        for (int e = 0; e < 8; e++) {
            acc[0][e] = ffma2(w01.x, x2[e], acc[0][e]);
            acc[1][e] = ffma2(w01.y, x2[e], acc[1][e]);
            acc[2][e] = ffma2(w23.x, x2[e], acc[2][e]);
            acc[3][e] = ffma2(w23.y, x2[e], acc[3][e]);
        }
    }

    u64t bb[4];
    #pragma unroll
    for (int jp = 0; jp < 4; jp++)
        bb[jp] = fpack2(__ldg(&b_ih[jg * 8 + 2 * jp]), __ldg(&b_ih[jg * 8 + 2 * jp + 1]));

    #pragma unroll
    for (int e = 0; e < 8; e++) {
        const int s = s0b + sg * 8 + e;
        if (s < Ns) {
            float2 v0 = funpack2(fadd2(acc[0][e], bb[0]));
            float2 v1 = funpack2(fadd2(acc[1][e], bb[1]));
            float2 v2 = funpack2(fadd2(acc[2][e], bb[2]));
            float2 v3 = funpack2(fadd2(acc[3][e], bb[3]));
            float4* o = reinterpret_cast<float4*>(&g_gi[((size_t)b * Ns + s) * 192 + jg * 8]);
            o[0] = make_float4(v0.x, v0.y, v1.x, v1.y);
            o[1] = make_float4(v2.x, v2.y, v3.x, v3.y);
        }
    }
}

// =====================================================================
// MEGA kernel: blocks [0,BSZ) = GRU (v4 body + progress publish);
//              blocks [BSZ,..) = fast (R4 body + progress spin).
// GRU blocks are all in dispatch wave 1 -> no deadlock.
// =====================================================================
__global__ void __launch_bounds__(128) mega_kernel(
    const float* __restrict__ W_hh, const float* __restrict__ b_hh,
    const float* __restrict__ W_cs, const float* __restrict__ b_cs,
    const float* __restrict__ x,
    const float* __restrict__ W1, const float* __restrict__ b1,
    const float* __restrict__ W2, const float* __restrict__ b2,
    int T, int Nf, int Ns)
{
    const int tid = threadIdx.x;

    if (blockIdx.x < BSZ) {
        // ---------------- GRU part (identical math to 809us version) ------
        __shared__ __align__(16) float h_sh[64];
        __shared__ float gh_sh[192];
        __shared__ float gi_sh[192];

        const int b = blockIdx.x;
        const bool is_gate = (tid < 96);

        u64t wA[32], wB[32];
        float bA = 0.f, bB = 0.f;
        if (is_gate) {
            const ulonglong2* rA = reinterpret_cast<const ulonglong2*>(W_hh + (size_t)tid * 64);
            const ulonglong2* rB = reinterpret_cast<const ulonglong2*>(W_hh + (size_t)(tid + 96) * 64);
            #pragma unroll
            for (int p = 0; p < 16; p++) {
                ulonglong2 a = rA[p]; wA[2*p] = a.x; wA[2*p+1] = a.y;
                ulonglong2 c = rB[p]; wB[2*p] = c.x; wB[2*p+1] = c.y;
            }
            bA = b_hh[tid]; bB = b_hh[tid + 96];
        } else {
            const ulonglong2* rA = reinterpret_cast<const ulonglong2*>(W_cs + (size_t)(tid - 96) * 64);
            #pragma unroll
            for (int p = 0; p < 16; p++) {
                ulonglong2 a = rA[p]; wA[2*p] = a.x; wA[2*p+1] = a.y;
                wB[2*p] = 0ULL; wB[2*p+1] = 0ULL;
            }
            bA = b_cs[tid - 96];
        }
        if (tid < 64) h_sh[tid] = 0.f;
        __syncthreads();

        const float* gib = g_gi + (size_t)b * Ns * 192;
        float*       csb = g_cs + (size_t)b * Ns * 32;

        float gA = 0.f, gB = 0.f;
        if (is_gate) { gA = __ldg(&gib[tid]); gB = __ldg(&gib[tid + 96]); }

        for (int t = 0; t < Ns; t++) {
            float gAn = 0.f, gBn = 0.f;
            if (is_gate && t + 1 < Ns) {
                gAn = __ldg(&gib[(size_t)(t + 1) * 192 + tid]);
                gBn = __ldg(&gib[(size_t)(t + 1) * 192 + tid + 96]);
            }

            const ulonglong2* hv = reinterpret_cast<const ulonglong2*>(h_sh);
            if (is_gate) {
                u64t a0 = 0ULL, a1 = 0ULL, c0 = 0ULL, c1 = 0ULL;
                #pragma unroll
                for (int p = 0; p < 16; p++) {
                    ulonglong2 h4 = hv[p];
                    a0 = ffma2(wA[2*p], h4.x, a0); a1 = ffma2(wA[2*p+1], h4.y, a1);
                    c0 = ffma2(wB[2*p], h4.x, c0); c1 = ffma2(wB[2*p+1], h4.y, c1);
                }
                gh_sh[tid]      = hsum2(fadd2(a0, a1)) + bA;
                gh_sh[tid + 96] = hsum2(fadd2(c0, c1)) + bB;
                gi_sh[tid]      = gA;
                gi_sh[tid + 96] = gB;
            } else {
                u64t a0 = 0ULL, a1 = 0ULL;
                #pragma unroll
                for (int p = 0; p < 16; p++) {
                    ulonglong2 h4 = hv[p];
                    a0 = ffma2(wA[2*p], h4.x, a0); a1 = ffma2(wA[2*p+1], h4.y, a1);
                }
                if (t > 0) csb[(size_t)(t - 1) * 32 + (tid - 96)] = hsum2(fadd2(a0, a1)) + bA;
                // publish progress every 16 steps: c_s[0..t-1] now written
                if (t > 0 && (t & 15) == 0) {
                    __threadfence();
                    __syncwarp(0xffffffffu);
                    if (tid == 96) atomicExch(&g_prog[b], t);
                }
            }
            __syncthreads();

            if (tid < 64) {
                const float r  = fast_sigmoid(gi_sh[tid]       + gh_sh[tid]      );
                const float z  = fast_sigmoid(gi_sh[tid + 64]  + gh_sh[tid + 64] );
                const float n  = fast_tanh   (gi_sh[tid + 128] + r * gh_sh[tid + 128]);
                h_sh[tid] = (1.f - z) * n + z * h_sh[tid];
            }
            __syncthreads();
            gA = gAn; gB = gBn;
        }

        if (!is_gate) {
            const ulonglong2* hv = reinterpret_cast<const ulonglong2*>(h_sh);
            u64t a0 = 0ULL, a1 = 0ULL;
            #pragma unroll
            for (int p = 0; p < 16; p++) {
                ulonglong2 h4 = hv[p];
                a0 = ffma2(wA[2*p], h4.x, a0); a1 = ffma2(wA[2*p+1], h4.y, a1);
            }
            csb[(size_t)(Ns - 1) * 32 + (tid - 96)] = hsum2(fadd2(a0, a1)) + bA;
            __threadfence();
            __syncwarp(0xffffffffu);
            if (tid == 96) atomicExch(&g_prog[b], Ns);   // all c_s ready
        }
        return;
    }

    // ---------------- FAST part (R4 body + spin on progress) --------------
    {
        __shared__ __align__(16) float W1sh[64 * 64];
        __shared__ __align__(16) float W2T[64 * 32];
        __shared__ float b1sh[64];
        __shared__ u64t  b2sh[16];

        const int fid   = blockIdx.x - BSZ;
        const int ftile = fid / BSZ;            // tile-major: early blocks need early progress
        const int b     = fid % BSZ;
        const int n0    = (ftile * 128 + tid) * 2;
        const int n1    = n0 + 1;

        for (int i = tid; i < 4096; i += 128) W1sh[i] = W1[i];
        for (int i = tid; i < 2048; i += 128) { int jj = i >> 5, ii = i & 31; W2T[i] = W2[ii * 64 + jj]; }
        if (tid < 64) b1sh[tid] = b1[tid];
        if (tid < 16) b2sh[tid] = fpack2(b2[2 * tid], b2[2 * tid + 1]);
        __syncthreads();

        // wait until the c_s range this tile needs is published
        {
            int nmax = ftile * 256 + 255; if (nmax > Nf - 1) nmax = Nf - 1;
            int cmax = nmax / 3 - 1; if (cmax < 0) cmax = 0;
            const int need = cmax + 1;
            if (tid == 0) {
                while (atomicAdd(&g_prog[b], 0) < need) __nanosleep(200);
            }
            __syncthreads();
            __threadfence();   // acquire: order c_s reads after flag observation
        }

        if (n0 >= Nf) return;
        const bool v1 = (n1 < Nf);

        u64t xf[24];
        {
            const float4* xp = reinterpret_cast<const float4*>(x + (size_t)b * T + (size_t)n0 * 16);
            #pragma unroll
            for (int q = 0; q < 12; q++) {
                float4 v = (q < 8 || v1) ? xp[q] : make_float4(0.f, 0.f, 0.f, 0.f);
                xf[2*q]   = fpack2(v.x, v.y);
                xf[2*q+1] = fpack2(v.z, v.w);
            }
        }
        u64t cf0[16], cf1[16];
        {
            int cn0 = n0 / 3 - 1; if (cn0 < 0) cn0 = 0;
            int cn1 = v1 ? (n1 / 3 - 1) : cn0; if (cn1 < 0) cn1 = 0;
            const ulonglong2* cp0 = reinterpret_cast<const ulonglong2*>(g_cs + ((size_t)b * Ns + cn0) * 32);
            const ulonglong2* cp1 = reinterpret_cast<const ulonglong2*>(g_cs + ((size_t)b * Ns + cn1) * 32);
            #pragma unroll
            for (int q = 0; q < 8; q++) {
                ulonglong2 u = cp0[q]; cf0[2*q] = u.x; cf0[2*q+1] = u.y;
                ulonglong2 w = cp1[q]; cf1[2*q] = w.x; cf1[2*q+1] = w.y;
            }
        }

        u64t ya[16], yb[16];
        #pragma unroll
        for (int i = 0; i < 16; i++) { ya[i] = 0ULL; yb[i] = 0ULL; }

        #pragma unroll 1
        for (int jj = 0; jj < 64; jj++) {
            const ulonglong2* w1v = reinterpret_cast<const ulonglong2*>(&W1sh[jj * 64]);
            u64t a0=0ULL,a1=0ULL,a2=0ULL,a3=0ULL;
            u64t c0=0ULL,c1=0ULL,c2=0ULL,c3=0ULL;
            #pragma unroll
            for (int p = 0; p < 8; p++) {
                ulonglong2 w = w1v[p];
                a0 = ffma2(w.x, xf[2*p],   a0); a1 = ffma2(w.y, xf[2*p+1],   a1);
                c0 = ffma2(w.x, xf[8+2*p], c0); c1 = ffma2(w.y, xf[8+2*p+1], c1);
            }
            #pragma unroll
            for (int p = 0; p < 8; p++) {
                ulonglong2 w = w1v[8 + p];
                a2 = ffma2(w.x, cf0[2*p], a2); a3 = ffma2(w.y, cf0[2*p+1], a3);
                c2 = ffma2(w.x, cf1[2*p], c2); c3 = ffma2(w.y, cf1[2*p+1], c3);
            }
            float hA = fmaxf(hsum2(fadd2(fadd2(a0,a1), fadd2(a2,a3))) + b1sh[jj], 0.f);
            float hB = fmaxf(hsum2(fadd2(fadd2(c0,c1), fadd2(c2,c3))) + b1sh[jj], 0.f);
            u64t hA2 = fpack2(hA, hA);
            u64t hB2 = fpack2(hB, hB);
            const ulonglong2* w2v = reinterpret_cast<const ulonglong2*>(&W2T[jj * 32]);
            #pragma unroll
            for (int p = 0; p < 8; p++) {
                ulonglong2 w = w2v[p];
                ya[2*p] = ffma2(w.x, hA2, ya[2*p]); ya[2*p+1] = ffma2(w.y, hA2, ya[2*p+1]);
                yb[2*p] = ffma2(w.x, hB2, yb[2*p]); yb[2*p+1] = ffma2(w.y, hB2, yb[2*p+1]);
            }
        }

        {
            float4* yo = reinterpret_cast<float4*>(&g_y[((size_t)b * Nf + n0) * 32]);
            #pragma unroll
            for (int p = 0; p < 8; p++) {
                float2 va = funpack2(fadd2(ya[2*p],     b2sh[2*p]));
                float2 vb = funpack2(fadd2(ya[2*p + 1], b2sh[2*p + 1]));
                yo[p] = make_float4(va.x, va.y, vb.x, vb.y);
            }
            if (v1) {
                float4* yo1 = reinterpret_cast<float4*>(&g_y[((size_t)b * Nf + n1) * 32]);
                #pragma unroll
                for (int p = 0; p < 8; p++) {
                    float2 va = funpack2(fadd2(yb[2*p],     b2sh[2*p]));
                    float2 vb = funpack2(fadd2(yb[2*p + 1], b2sh[2*p + 1]));
                    yo1[p] = make_float4(va.x, va.y, vb.x, vb.y);
                }
            }
        }
    }
}

// =====================================================================
// Kernel D: overlap-add as gather (each sample covered by <=2 frames).
// =====================================================================
__global__ void __launch_bounds__(256) gather_kernel(float* __restrict__ out,
                                                     int T, int Nf) {
    const int idx = blockIdx.x * blockDim.x + threadIdx.x;
    const int total = BSZ * T;
    if (idx >= total) return;
    const int b = idx / T, t = idx % T;
    const int n0 = t >> 4, r = t & 15;
    const float* yb = g_y + (size_t)b * Nf * 32;
    float v = 0.f;
    if (n0 < Nf)                 v += yb[n0 * 32 + r];
    if (n0 >= 1 && n0 - 1 < Nf)  v += yb[(n0 - 1) * 32 + 16 + r];
    out[idx] = v;
}

// =====================================================================
extern "C" void kernel_launch(void* const* d_in, const int* in_sizes, int n_in,
                              void* d_out, int out_size) {
    const float* x    = (const float*)d_in[0];
    const float* W_ih = (const float*)d_in[1];
    const float* W_hh = (const float*)d_in[2];
    const float* b_ih = (const float*)d_in[3];
    const float* b_hh = (const float*)d_in[4];
    const float* W_cs = (const float*)d_in[5];
    const float* b_cs = (const float*)d_in[6];
    const float* W1   = (const float*)d_in[7];
    const float* b1   = (const float*)d_in[8];
    const float* W2   = (const float*)d_in[9];
    const float* b2   = (const float*)d_in[10];
    float* out = (float*)d_out;

    const int T  = in_sizes[0] / BSZ;
    const int Nf = (T - 32) / 16 + 1;
    const int Ns = (T - 96) / 48 + 1;

    const int GI_SMEM = (18432 + 96 * XST) * (int)sizeof(float);   // ~101 KB
    cudaFuncSetAttribute(gi_kernel, cudaFuncAttributeMaxDynamicSharedMemorySize, GI_SMEM);

    const int fastBlocks = ((Nf + 255) / 256) * BSZ;

    prep_kernel  <<<1, 256>>>(W_ih);
    gi_kernel    <<<dim3((Ns + GI_STILE - 1) / GI_STILE, BSZ), 192, GI_SMEM>>>(x, b_ih, T, Ns);
    mega_kernel  <<<BSZ + fastBlocks, 128>>>(W_hh, b_hh, W_cs, b_cs,
                                             x, W1, b1, W2, b2, T, Nf, Ns);
    gather_kernel<<<(BSZ * T + 255) / 256, 256>>>(out, T, Nf);
}

// round 14
// speedup vs baseline: 1.6095x; 1.0528x over previous
#include <cuda_runtime.h>
#include <cuda_bf16.h>
#include <cstdint>

// Shapes fixed by dataset: L_F=32, HOP=16, DELTA=3, L_S=96, COND=32, GH=64, B=128, T=48000
// Nf = 2999, Ns = 999
#define BSZ    128
#define NS_MAX 999
#define NF_MAX 2999
#define NCHUNK 8
#define WARMUP 128

typedef unsigned long long u64t;

// ---------------- packed f32x2 helpers (sm_103a FFMA2 path) ----------------
__device__ __forceinline__ u64t ffma2(u64t a, u64t b, u64t c) {
    u64t d; asm("fma.rn.f32x2 %0, %1, %2, %3;" : "=l"(d) : "l"(a), "l"(b), "l"(c)); return d;
}
__device__ __forceinline__ u64t fadd2(u64t a, u64t b) {
    u64t d; asm("add.rn.f32x2 %0, %1, %2;" : "=l"(d) : "l"(a), "l"(b)); return d;
}
__device__ __forceinline__ u64t fpack2(float lo, float hi) {
    u64t d; asm("mov.b64 %0, {%1, %2};" : "=l"(d) : "f"(lo), "f"(hi)); return d;
}
__device__ __forceinline__ float2 funpack2(u64t v) {
    float2 f; asm("mov.b64 {%0, %1}, %2;" : "=f"(f.x), "=f"(f.y) : "l"(v)); return f;
}
__device__ __forceinline__ float hsum2(u64t v) { float2 f = funpack2(v); return f.x + f.y; }

// ---------------- fast transcendentals (MUFU; err ~1e-7, budget 1e-3) ------
__device__ __forceinline__ float fast_ex2(float x) {
    float y; asm("ex2.approx.f32 %0, %1;" : "=f"(y) : "f"(x)); return y;
}
__device__ __forceinline__ float fast_rcp(float x) {
    float y; asm("rcp.approx.f32 %0, %1;" : "=f"(y) : "f"(x)); return y;
}
__device__ __forceinline__ float fast_sigmoid(float v) {
    return fast_rcp(1.f + fast_ex2(-1.4426950408889634f * v));
}
__device__ __forceinline__ float fast_tanh(float v) {
    return 2.f * fast_rcp(1.f + fast_ex2(-2.8853900817779268f * v)) - 1.f;
}

// ---------------- scratch (device globals; no allocations allowed) ----------
__device__ float g_gi  [(size_t)BSZ * NS_MAX * 192];
__device__ float g_cs  [(size_t)BSZ * NS_MAX * 32];
__device__ float g_y   [(size_t)BSZ * NF_MAX * 32];
__device__ float g_WihT[96 * 192];
__device__ int   g_cdone[BSZ * NCHUNK];   // per (batch,chunk) completion flag

// =====================================================================
// Kernel P: one-time transpose W_ihT[k][j] = W_ih[j][k]; reset flags.
// =====================================================================
__global__ void __launch_bounds__(256) prep_kernel(const float* __restrict__ W_ih) {
    for (int i = threadIdx.x; i < BSZ * NCHUNK; i += 256) g_cdone[i] = 0;
    for (int idx = threadIdx.x; idx < 192 * 96; idx += 256) {
        int j = idx / 96, k = idx % 96;
        g_WihT[k * 192 + j] = W_ih[idx];
    }
}

// =====================================================================
// Kernel A v4 (unchanged): register-tiled GEMM for gi.
// =====================================================================
#define GI_STILE 64
#define XST 72
__global__ void __launch_bounds__(192) gi_kernel(const float* __restrict__ x,
                                                 const float* __restrict__ b_ih,
                                                 int T, int Ns) {
    extern __shared__ float smem[];
    float* Wsh   = smem;
    float* xpadT = smem + 18432;

    const int b   = blockIdx.y;
    const int s0b = blockIdx.x * GI_STILE;
    const int tid = threadIdx.x;
    const int jg  = tid >> 3;
    const int sg  = tid & 7;

    {
        const float4* wsrc = reinterpret_cast<const float4*>(g_WihT);
        float4*       wdst = reinterpret_cast<float4*>(Wsh);
        for (int i = tid; i < 18432 / 4; i += 192) wdst[i] = wsrc[i];
    }
    {
        const float* xb = x + (size_t)b * T;
        for (int idx = tid; idx < 96 * GI_STILE; idx += 192) {
            int s = idx / 96, k = idx % 96;
            int g = (s0b + s) * 48 + k;
            xpadT[k * XST + s] = (g < T) ? xb[g] : 0.f;
        }
    }
    __syncthreads();

    u64t acc[4][8];
    #pragma unroll
    for (int jp = 0; jp < 4; jp++)
        #pragma unroll
        for (int e = 0; e < 8; e++) acc[jp][e] = 0ULL;

    #pragma unroll 4
    for (int k = 0; k < 96; k++) {
        const ulonglong2* wp = reinterpret_cast<const ulonglong2*>(&Wsh[k * 192 + jg * 8]);
        const ulonglong2 w01 = wp[0];
        const ulonglong2 w23 = wp[1];
        const float4 xa  = *reinterpret_cast<const float4*>(&xpadT[k * XST + sg * 8]);
        const float4 xb4 = *reinterpret_cast<const float4*>(&xpadT[k * XST + sg * 8 + 4]);
        u64t x2[8];
        x2[0] = fpack2(xa.x, xa.x);   x2[1] = fpack2(xa.y, xa.y);
        x2[2] = fpack2(xa.z, xa.z);   x2[3] = fpack2(xa.w, xa.w);
        x2[4] = fpack2(xb4.x, xb4.x); x2[5] = fpack2(xb4.y, xb4.y);
        x2[6] = fpack2(xb4.z, xb4.z); x2[7] = fpack2(xb4.w, xb4.w);
        #pragma unroll
        for (int e = 0; e < 8; e++) {
            acc[0][e] = ffma2(w01.x, x2[e], acc[0][e]);
            acc[1][e] = ffma2(w01.y, x2[e], acc[1][e]);
            acc[2][e] = ffma2(w23.x, x2[e], acc[2][e]);
            acc[3][e] = ffma2(w23.y, x2[e], acc[3][e]);
        }
    }

    u64t bb[4];
    #pragma unroll
    for (int jp = 0; jp < 4; jp++)
        bb[jp] = fpack2(__ldg(&b_ih[jg * 8 + 2 * jp]), __ldg(&b_ih[jg * 8 + 2 * jp + 1]));

    #pragma unroll
    for (int e = 0; e < 8; e++) {
        const int s = s0b + sg * 8 + e;
        if (s < Ns) {
            float2 v0 = funpack2(fadd2(acc[0][e], bb[0]));
            float2 v1 = funpack2(fadd2(acc[1][e], bb[1]));
            float2 v2 = funpack2(fadd2(acc[2][e], bb[2]));
            float2 v3 = funpack2(fadd2(acc[3][e], bb[3]));
            float4* o = reinterpret_cast<float4*>(&g_gi[((size_t)b * Ns + s) * 192 + jg * 8]);
            o[0] = make_float4(v0.x, v0.y, v1.x, v1.y);
            o[1] = make_float4(v2.x, v2.y, v3.x, v3.y);
        }
    }
}

// =====================================================================
// MEGA kernel:
//   blocks [0, BSZ*NCHUNK)        = GRU chunk (b, c): warm-up from h=0 at
//                                   t0-WARMUP, store c_s over [t0, t1).
//   blocks [BSZ*NCHUNK, ..)       = fast (R4 body + chunk-flag spin).
// =====================================================================
__global__ void __launch_bounds__(128) mega_kernel(
    const float* __restrict__ W_hh, const float* __restrict__ b_hh,
    const float* __restrict__ W_cs, const float* __restrict__ b_cs,
    const float* __restrict__ x,
    const float* __restrict__ W1, const float* __restrict__ b1,
    const float* __restrict__ W2, const float* __restrict__ b2,
    int T, int Nf, int Ns, int L)
{
    const int tid = threadIdx.x;

    if (blockIdx.x < BSZ * NCHUNK) {
        // ---------------- GRU chunk ---------------------------------------
        const int b  = blockIdx.x / NCHUNK;
        const int c  = blockIdx.x % NCHUNK;
        const int t0 = c * L;
        if (t0 >= Ns) {                       // empty chunk: mark done
            if (tid == 0) atomicExch(&g_cdone[b * NCHUNK + c], 1);
            return;
        }
        int t1 = t0 + L; if (t1 > Ns) t1 = Ns;
        int tw = t0 - WARMUP; if (tw < 0) tw = 0;

        __shared__ __align__(16) float h_sh[64];
        __shared__ float gh_sh[192];
        __shared__ float gi_sh[192];

        const bool is_gate = (tid < 96);

        u64t wA[32], wB[32];
        float bA = 0.f, bB = 0.f;
        if (is_gate) {
            const ulonglong2* rA = reinterpret_cast<const ulonglong2*>(W_hh + (size_t)tid * 64);
            const ulonglong2* rB = reinterpret_cast<const ulonglong2*>(W_hh + (size_t)(tid + 96) * 64);
            #pragma unroll
            for (int p = 0; p < 16; p++) {
                ulonglong2 a = rA[p]; wA[2*p] = a.x; wA[2*p+1] = a.y;
                ulonglong2 cc = rB[p]; wB[2*p] = cc.x; wB[2*p+1] = cc.y;
            }
            bA = b_hh[tid]; bB = b_hh[tid + 96];
        } else {
            const ulonglong2* rA = reinterpret_cast<const ulonglong2*>(W_cs + (size_t)(tid - 96) * 64);
            #pragma unroll
            for (int p = 0; p < 16; p++) {
                ulonglong2 a = rA[p]; wA[2*p] = a.x; wA[2*p+1] = a.y;
                wB[2*p] = 0ULL; wB[2*p+1] = 0ULL;
            }
            bA = b_cs[tid - 96];
        }
        if (tid < 64) h_sh[tid] = 0.f;
        __syncthreads();

        const float* gib = g_gi + (size_t)b * Ns * 192;
        float*       csb = g_cs + (size_t)b * Ns * 32;

        float gA = 0.f, gB = 0.f;
        if (is_gate) {
            gA = __ldg(&gib[(size_t)tw * 192 + tid]);
            gB = __ldg(&gib[(size_t)tw * 192 + tid + 96]);
        }

        for (int t = tw; t < t1; t++) {
            float gAn = 0.f, gBn = 0.f;
            if (is_gate && t + 1 < t1) {
                gAn = __ldg(&gib[(size_t)(t + 1) * 192 + tid]);
                gBn = __ldg(&gib[(size_t)(t + 1) * 192 + tid + 96]);
            }

            const ulonglong2* hv = reinterpret_cast<const ulonglong2*>(h_sh);
            if (is_gate) {
                u64t a0 = 0ULL, a1 = 0ULL, c0 = 0ULL, c1 = 0ULL;
                #pragma unroll
                for (int p = 0; p < 16; p++) {
                    ulonglong2 h4 = hv[p];
                    a0 = ffma2(wA[2*p], h4.x, a0); a1 = ffma2(wA[2*p+1], h4.y, a1);
                    c0 = ffma2(wB[2*p], h4.x, c0); c1 = ffma2(wB[2*p+1], h4.y, c1);
                }
                gh_sh[tid]      = hsum2(fadd2(a0, a1)) + bA;
                gh_sh[tid + 96] = hsum2(fadd2(c0, c1)) + bB;
                gi_sh[tid]      = gA;
                gi_sh[tid + 96] = gB;
            } else {
                // c_s[t-1] from hs[t-1]; only store inside this chunk's range
                if (t - 1 >= t0) {
                    u64t a0 = 0ULL, a1 = 0ULL;
                    #pragma unroll
                    for (int p = 0; p < 16; p++) {
                        ulonglong2 h4 = hv[p];
                        a0 = ffma2(wA[2*p], h4.x, a0); a1 = ffma2(wA[2*p+1], h4.y, a1);
                    }
                    csb[(size_t)(t - 1) * 32 + (tid - 96)] = hsum2(fadd2(a0, a1)) + bA;
                }
            }
            __syncthreads();

            if (tid < 64) {
                const float r  = fast_sigmoid(gi_sh[tid]       + gh_sh[tid]      );
                const float z  = fast_sigmoid(gi_sh[tid + 64]  + gh_sh[tid + 64] );
                const float n  = fast_tanh   (gi_sh[tid + 128] + r * gh_sh[tid + 128]);
                h_sh[tid] = (1.f - z) * n + z * h_sh[tid];
            }
            __syncthreads();
            gA = gAn; gB = gBn;
        }

        // tail: c_s[t1-1] from hs[t1-1], then publish chunk completion
        if (!is_gate) {
            const ulonglong2* hv = reinterpret_cast<const ulonglong2*>(h_sh);
            u64t a0 = 0ULL, a1 = 0ULL;
            #pragma unroll
            for (int p = 0; p < 16; p++) {
                ulonglong2 h4 = hv[p];
                a0 = ffma2(wA[2*p], h4.x, a0); a1 = ffma2(wA[2*p+1], h4.y, a1);
            }
            csb[(size_t)(t1 - 1) * 32 + (tid - 96)] = hsum2(fadd2(a0, a1)) + bA;
            __threadfence();
            __syncwarp(0xffffffffu);
            if (tid == 96) atomicExch(&g_cdone[b * NCHUNK + c], 1);
        }
        return;
    }

    // ---------------- FAST part (R4 body + chunk-flag spin) ----------------
    {
        __shared__ __align__(16) float W1sh[64 * 64];
        __shared__ __align__(16) float W2T[64 * 32];
        __shared__ float b1sh[64];
        __shared__ u64t  b2sh[16];

        const int fid   = blockIdx.x - BSZ * NCHUNK;
        const int ftile = fid / BSZ;
        const int b     = fid % BSZ;
        const int n0    = (ftile * 128 + tid) * 2;
        const int n1    = n0 + 1;

        for (int i = tid; i < 4096; i += 128) W1sh[i] = W1[i];
        for (int i = tid; i < 2048; i += 128) { int jj = i >> 5, ii = i & 31; W2T[i] = W2[ii * 64 + jj]; }
        if (tid < 64) b1sh[tid] = b1[tid];
        if (tid < 16) b2sh[tid] = fpack2(b2[2 * tid], b2[2 * tid + 1]);
        __syncthreads();

        // wait for every chunk covering c_s[0..cmax]
        {
            int nmax = ftile * 256 + 255; if (nmax > Nf - 1) nmax = Nf - 1;
            int cmax = nmax / 3 - 1; if (cmax < 0) cmax = 0;
            int cidx = cmax / L; if (cidx > NCHUNK - 1) cidx = NCHUNK - 1;
            if (tid == 0) {
                for (int k = 0; k <= cidx; k++)
                    while (atomicAdd(&g_cdone[b * NCHUNK + k], 0) == 0) __nanosleep(200);
            }
            __syncthreads();
            __threadfence();
        }

        if (n0 >= Nf) return;
        const bool v1 = (n1 < Nf);

        u64t xf[24];
        {
            const float4* xp = reinterpret_cast<const float4*>(x + (size_t)b * T + (size_t)n0 * 16);
            #pragma unroll
            for (int q = 0; q < 12; q++) {
                float4 v = (q < 8 || v1) ? xp[q] : make_float4(0.f, 0.f, 0.f, 0.f);
                xf[2*q]   = fpack2(v.x, v.y);
                xf[2*q+1] = fpack2(v.z, v.w);
            }
        }
        u64t cf0[16], cf1[16];
        {
            int cn0 = n0 / 3 - 1; if (cn0 < 0) cn0 = 0;
            int cn1 = v1 ? (n1 / 3 - 1) : cn0; if (cn1 < 0) cn1 = 0;
            const ulonglong2* cp0 = reinterpret_cast<const ulonglong2*>(g_cs + ((size_t)b * Ns + cn0) * 32);
            const ulonglong2* cp1 = reinterpret_cast<const ulonglong2*>(g_cs + ((size_t)b * Ns + cn1) * 32);
            #pragma unroll
            for (int q = 0; q < 8; q++) {
                ulonglong2 u = cp0[q]; cf0[2*q] = u.x; cf0[2*q+1] = u.y;
                ulonglong2 w = cp1[q]; cf1[2*q] = w.x; cf1[2*q+1] = w.y;
            }
        }

        u64t ya[16], yb[16];
        #pragma unroll
        for (int i = 0; i < 16; i++) { ya[i] = 0ULL; yb[i] = 0ULL; }

        #pragma unroll 1
        for (int jj = 0; jj < 64; jj++) {
            const ulonglong2* w1v = reinterpret_cast<const ulonglong2*>(&W1sh[jj * 64]);
            u64t a0=0ULL,a1=0ULL,a2=0ULL,a3=0ULL;
            u64t c0=0ULL,c1=0ULL,c2=0ULL,c3=0ULL;
            #pragma unroll
            for (int p = 0; p < 8; p++) {
                ulonglong2 w = w1v[p];
                a0 = ffma2(w.x, xf[2*p],   a0); a1 = ffma2(w.y, xf[2*p+1],   a1);
                c0 = ffma2(w.x, xf[8+2*p], c0); c1 = ffma2(w.y, xf[8+2*p+1], c1);
            }
            #pragma unroll
            for (int p = 0; p < 8; p++) {
                ulonglong2 w = w1v[8 + p];
                a2 = ffma2(w.x, cf0[2*p], a2); a3 = ffma2(w.y, cf0[2*p+1], a3);
                c2 = ffma2(w.x, cf1[2*p], c2); c3 = ffma2(w.y, cf1[2*p+1], c3);
            }
            float hA = fmaxf(hsum2(fadd2(fadd2(a0,a1), fadd2(a2,a3))) + b1sh[jj], 0.f);
            float hB = fmaxf(hsum2(fadd2(fadd2(c0,c1), fadd2(c2,c3))) + b1sh[jj], 0.f);
            u64t hA2 = fpack2(hA, hA);
            u64t hB2 = fpack2(hB, hB);
            const ulonglong2* w2v = reinterpret_cast<const ulonglong2*>(&W2T[jj * 32]);
            #pragma unroll
            for (int p = 0; p < 8; p++) {
                ulonglong2 w = w2v[p];
                ya[2*p] = ffma2(w.x, hA2, ya[2*p]); ya[2*p+1] = ffma2(w.y, hA2, ya[2*p+1]);
                yb[2*p] = ffma2(w.x, hB2, yb[2*p]); yb[2*p+1] = ffma2(w.y, hB2, yb[2*p+1]);
            }
        }

        {
            float4* yo = reinterpret_cast<float4*>(&g_y[((size_t)b * Nf + n0) * 32]);
            #pragma unroll
            for (int p = 0; p < 8; p++) {
                float2 va = funpack2(fadd2(ya[2*p],     b2sh[2*p]));
                float2 vb = funpack2(fadd2(ya[2*p + 1], b2sh[2*p + 1]));
                yo[p] = make_float4(va.x, va.y, vb.x, vb.y);
            }
            if (v1) {
                float4* yo1 = reinterpret_cast<float4*>(&g_y[((size_t)b * Nf + n1) * 32]);
                #pragma unroll
                for (int p = 0; p < 8; p++) {
                    float2 va = funpack2(fadd2(yb[2*p],     b2sh[2*p]));
                    float2 vb = funpack2(fadd2(yb[2*p + 1], b2sh[2*p + 1]));
                    yo1[p] = make_float4(va.x, va.y, vb.x, vb.y);
                }
            }
        }
    }
}

// =====================================================================
// Kernel D: overlap-add as gather (each sample covered by <=2 frames).
// =====================================================================
__global__ void __launch_bounds__(256) gather_kernel(float* __restrict__ out,
                                                     int T, int Nf) {
    const int idx = blockIdx.x * blockDim.x + threadIdx.x;
    const int total = BSZ * T;
    if (idx >= total) return;
    const int b = idx / T, t = idx % T;
    const int n0 = t >> 4, r = t & 15;
    const float* yb = g_y + (size_t)b * Nf * 32;
    float v = 0.f;
    if (n0 < Nf)                 v += yb[n0 * 32 + r];
    if (n0 >= 1 && n0 - 1 < Nf)  v += yb[(n0 - 1) * 32 + 16 + r];
    out[idx] = v;
}

// =====================================================================
extern "C" void kernel_launch(void* const* d_in, const int* in_sizes, int n_in,
                              void* d_out, int out_size) {
    const float* x    = (const float*)d_in[0];
    const float* W_ih = (const float*)d_in[1];
    const float* W_hh = (const float*)d_in[2];
    const float* b_ih = (const float*)d_in[3];
    const float* b_hh = (const float*)d_in[4];
    const float* W_cs = (const float*)d_in[5];
    const float* b_cs = (const float*)d_in[6];
    const float* W1   = (const float*)d_in[7];
    const float* b1   = (const float*)d_in[8];
    const float* W2   = (const float*)d_in[9];
    const float* b2   = (const float*)d_in[10];
    float* out = (float*)d_out;

    const int T  = in_sizes[0] / BSZ;
    const int Nf = (T - 32) / 16 + 1;
    const int Ns = (T - 96) / 48 + 1;
    const int L  = (Ns + NCHUNK - 1) / NCHUNK;   // chunk length (125)

    const int GI_SMEM = (18432 + 96 * XST) * (int)sizeof(float);   // ~101 KB
    cudaFuncSetAttribute(gi_kernel, cudaFuncAttributeMaxDynamicSharedMemorySize, GI_SMEM);

    const int fastBlocks = ((Nf + 255) / 256) * BSZ;

    prep_kernel  <<<1, 256>>>(W_ih);
    gi_kernel    <<<dim3((Ns + GI_STILE - 1) / GI_STILE, BSZ), 192, GI_SMEM>>>(x, b_ih, T, Ns);
    mega_kernel  <<<BSZ * NCHUNK + fastBlocks, 128>>>(W_hh, b_hh, W_cs, b_cs,
                                                      x, W1, b1, W2, b2, T, Nf, Ns, L);
    gather_kernel<<<(BSZ * T + 255) / 256, 256>>>(out, T, Nf);
}